// round 5
// baseline (speedup 1.0000x reference)
#include <cuda_runtime.h>
#include <math.h>

#define B_  4
#define N_  4096
#define D_  244
#define DP_ 256
#define M_  (B_*N_)

// scratch (device globals: no runtime allocation allowed)
__device__ float g_V[(size_t)M_*DP_];
__device__ float g_P[(size_t)M_*DP_];

// ---------------------------------------------------------------------------
// GEMM + bias:  C[r][c] = sum_k A[r][k] * W[c][k] + bias[c]   (torch Linear)
// K logically 244, padded loop to 256 with zero guards.
// Smem tiles padded to pitch 68 (multiple of 4) so float4 LDS are aligned.
// ---------------------------------------------------------------------------
__global__ __launch_bounds__(256, 4) void gemm_bias_kernel(
    const float* __restrict__ A, int lda,
    const float* __restrict__ W,
    const float* __restrict__ bias,
    float* __restrict__ C, int ldc, int cw)
{
    __shared__ float AsT[16][68];
    __shared__ float WsT[16][68];
    const int t  = threadIdx.x;
    const int ti = t & 15, tj = t >> 4;
    const int r0 = blockIdx.x * 64;
    const int c0 = blockIdx.y * 64;
    const int lr = t >> 2;
    const int lq = t & 3;
    float acc[4][4] = {};

    for (int k0 = 0; k0 < 256; k0 += 16) {
        const int k = k0 + lq * 4;
        float4 av = make_float4(0.f, 0.f, 0.f, 0.f);
        if (k < D_) av = *(const float4*)(A + (size_t)(r0 + lr) * lda + k);
        float4 wv = make_float4(0.f, 0.f, 0.f, 0.f);
        const int wr = c0 + lr;
        if (k < D_ && wr < D_) wv = *(const float4*)(W + (size_t)wr * D_ + k);
        __syncthreads();
        AsT[lq*4+0][lr] = av.x; AsT[lq*4+1][lr] = av.y;
        AsT[lq*4+2][lr] = av.z; AsT[lq*4+3][lr] = av.w;
        WsT[lq*4+0][lr] = wv.x; WsT[lq*4+1][lr] = wv.y;
        WsT[lq*4+2][lr] = wv.z; WsT[lq*4+3][lr] = wv.w;
        __syncthreads();
        #pragma unroll
        for (int kk = 0; kk < 16; kk++) {
            float4 a4 = *(const float4*)&AsT[kk][ti*4];
            float4 w4 = *(const float4*)&WsT[kk][tj*4];
            float aa[4] = {a4.x, a4.y, a4.z, a4.w};
            float ww[4] = {w4.x, w4.y, w4.z, w4.w};
            #pragma unroll
            for (int i = 0; i < 4; i++)
                #pragma unroll
                for (int j = 0; j < 4; j++)
                    acc[i][j] += aa[i] * ww[j];
        }
    }
    #pragma unroll
    for (int i = 0; i < 4; i++) {
        const int r = r0 + ti*4 + i;
        const int c = c0 + tj*4;
        float o[4];
        #pragma unroll
        for (int j = 0; j < 4; j++) {
            const float bz = (c + j < D_) ? bias[c + j] : 0.f;
            o[j] = acc[i][j] + bz;
        }
        float* cp = C + (size_t)r * ldc + c;
        if (c + 3 < cw) {
            *(float4*)cp = make_float4(o[0], o[1], o[2], o[3]);
        } else {
            #pragma unroll
            for (int j = 0; j < 4; j++) if (c + j < cw) cp[j] = o[j];
        }
    }
}

// ---------------------------------------------------------------------------
// Fused physics-attention.
// For each row n: Z = sum_all_m exp(-e), S = sum_{m<=n} exp(-e),
// numer[d] = sum_{m<=n} exp(-e)*V[m][d],
// out = scale * numer / (scale*S + 1e-8*Z), scale = min(valence/(1+1e-6),1).
// (Exactly equal to the reference chain: softmax -> *scale -> mask -> renorm;
//  max-subtraction cancels; logits bounded so no overflow in fp32.)
// ---------------------------------------------------------------------------
#define PADQ 68
#define SMEM_FLOATS (2*64*PADQ + 64*65 + 64*256 + 5*64)

__global__ __launch_bounds__(256, 1) void attn_kernel(
    const float* __restrict__ charge,
    const float* __restrict__ shell,
    const float* __restrict__ mass,
    const float* __restrict__ valence)
{
    extern __shared__ float smem[];
    float* sqT  = smem;               // [64][PADQ] shell_q transposed (k-dim major)
    float* skT  = sqT + 64*PADQ;      // [64][PADQ] shell_k transposed
    float* sp   = skT + 64*PADQ;      // [64][65] p tile (row, m) — scalar access only
    float* sv   = sp  + 64*65;        // [64][256] V tile (padded)
    float* scq  = sv  + 64*256;       // [64] q charge
    float* ssq  = scq + 64;           // [64] sqrt(mass) q
    float* sck  = ssq + 64;           // [64] k charge
    float* ssk  = sck + 64;           // [64] sqrt(mass) k
    float* sfac = ssk + 64;           // [64] final per-row factor
    float* red  = skT;                // reused as [64][17] reduce buffer at end

    const int t  = threadIdx.x;
    const int b  = blockIdx.y;
    const int rb = 63 - (int)blockIdx.x;   // heavy row-blocks first
    const int r0 = rb * 64;

    // ---- load q-side (transposed shell + scalars) ----
    {
        const float* shq = shell + ((size_t)b * N_ + r0) * 64;
        #pragma unroll
        for (int j = 0; j < 4; j++) {
            const int idx = t + j*256;         // 1024 float4s
            const int r = idx >> 4, s4 = idx & 15;
            float4 v = *(const float4*)(shq + r*64 + s4*4);
            sqT[(s4*4+0)*PADQ + r] = v.x;
            sqT[(s4*4+1)*PADQ + r] = v.y;
            sqT[(s4*4+2)*PADQ + r] = v.z;
            sqT[(s4*4+3)*PADQ + r] = v.w;
        }
        if (t < 64) {
            scq[t] = charge[(size_t)b * N_ + r0 + t];
            ssq[t] = sqrtf(mass[(size_t)b * N_ + r0 + t]);
        }
    }

    const int tr = t & 15, tc = t >> 4;        // score mapping: rows 4tr.., cols 4tc..
    const int w  = t >> 5, l  = t & 31;        // AV mapping: warp rows, lane cols
    float zpart[4] = {0.f, 0.f, 0.f, 0.f};
    float spart[4] = {0.f, 0.f, 0.f, 0.f};
    float accv[8][8];
    #pragma unroll
    for (int i = 0; i < 8; i++)
        #pragma unroll
        for (int j = 0; j < 8; j++) accv[i][j] = 0.f;

    for (int mt = 0; mt < 64; mt++) {
        const int  m0 = mt * 64;
        const bool need_av = (m0 <= r0 + 63);  // tile intersects causal region
        __syncthreads();                       // prev tile fully consumed
        // ---- load k-side tile ----
        {
            const float* shk = shell + ((size_t)b * N_ + m0) * 64;
            #pragma unroll
            for (int j = 0; j < 4; j++) {
                const int idx = t + j*256;
                const int r = idx >> 4, s4 = idx & 15;
                float4 v = *(const float4*)(shk + r*64 + s4*4);
                skT[(s4*4+0)*PADQ + r] = v.x;
                skT[(s4*4+1)*PADQ + r] = v.y;
                skT[(s4*4+2)*PADQ + r] = v.z;
                skT[(s4*4+3)*PADQ + r] = v.w;
            }
            if (t < 64) {
                sck[t] = charge[(size_t)b * N_ + m0 + t];
                ssk[t] = sqrtf(mass[(size_t)b * N_ + m0 + t]);
            }
            if (need_av) {
                const float* vg = g_V + ((size_t)b * N_ + m0) * DP_;
                #pragma unroll
                for (int j = 0; j < 16; j++) {
                    const int idx = t + j*256;  // 4096 float4s
                    *(float4*)(sv + idx*4) = *(const float4*)(vg + idx*4);
                }
            }
        }
        __syncthreads();
        // ---- scores: 64x64 shell dot (outer product form) ----
        float pa[4][4] = {};
        #pragma unroll 8
        for (int kk = 0; kk < 64; kk++) {
            float4 q4 = *(const float4*)&sqT[kk*PADQ + tr*4];
            float4 k4 = *(const float4*)&skT[kk*PADQ + tc*4];
            float qa[4] = {q4.x, q4.y, q4.z, q4.w};
            float ka[4] = {k4.x, k4.y, k4.z, k4.w};
            #pragma unroll
            for (int i = 0; i < 4; i++)
                #pragma unroll
                for (int j = 0; j < 4; j++)
                    pa[i][j] += qa[i] * ka[j];
        }
        // ---- energy -> exp, accumulate Z/S, store masked p ----
        #pragma unroll
        for (int i = 0; i < 4; i++) {
            const int r  = tr*4 + i;
            const int ng = r0 + r;
            const float cq = scq[r];
            const float sq = ssq[r];
            #pragma unroll
            for (int j = 0; j < 4; j++) {
                const int mc = tc*4 + j;
                const int mg = m0 + mc;
                const float e = cq * sck[mc] + 0.5f * pa[i][j]
                              + 0.3f * fabsf((float)(ng - mg))
                              + 0.1f * sq * ssk[mc];
                float p = __expf(-e);
                zpart[i] += p;
                p = (mg <= ng) ? p : 0.f;
                spart[i] += p;
                sp[r*65 + mc] = p;
            }
        }
        __syncthreads();
        // ---- AV accumulate (causal tiles only) ----
        if (need_av) {
            #pragma unroll 2
            for (int m = 0; m < 64; m++) {
                const float4 v0 = *(const float4*)(sv + m*256 + l*8);
                const float4 v1 = *(const float4*)(sv + m*256 + l*8 + 4);
                #pragma unroll
                for (int ri = 0; ri < 8; ri++) {
                    const float pw = sp[(w*8 + ri)*65 + m];
                    accv[ri][0] += pw * v0.x; accv[ri][1] += pw * v0.y;
                    accv[ri][2] += pw * v0.z; accv[ri][3] += pw * v0.w;
                    accv[ri][4] += pw * v1.x; accv[ri][5] += pw * v1.y;
                    accv[ri][6] += pw * v1.z; accv[ri][7] += pw * v1.w;
                }
            }
        }
    }
    __syncthreads();
    // ---- cross-thread reductions of Z and S per row ----
    #pragma unroll
    for (int i = 0; i < 4; i++) red[(tr*4 + i)*17 + tc] = zpart[i];
    __syncthreads();
    float Zr = 0.f;
    if (t < 64) {
        #pragma unroll
        for (int g = 0; g < 16; g++) Zr += red[t*17 + g];
    }
    __syncthreads();
    #pragma unroll
    for (int i = 0; i < 4; i++) red[(tr*4 + i)*17 + tc] = spart[i];
    __syncthreads();
    if (t < 64) {
        float S = 0.f;
        #pragma unroll
        for (int g = 0; g < 16; g++) S += red[t*17 + g];
        const float val   = valence[(size_t)b * N_ + r0 + t];
        const float scale = fminf(val / (1.f + 1e-6f), 1.f);
        sfac[t] = scale / (scale * S + 1e-8f * Zr);
    }
    __syncthreads();
    // ---- write out_pre ----
    #pragma unroll
    for (int ri = 0; ri < 8; ri++) {
        const int r = w*8 + ri;
        const float f = sfac[r];
        float* op = g_P + ((size_t)b * N_ + r0 + r) * DP_ + l*8;
        *(float4*)(op)     = make_float4(accv[ri][0]*f, accv[ri][1]*f,
                                         accv[ri][2]*f, accv[ri][3]*f);
        *(float4*)(op + 4) = make_float4(accv[ri][4]*f, accv[ri][5]*f,
                                         accv[ri][6]*f, accv[ri][7]*f);
    }
}

// ---------------------------------------------------------------------------
extern "C" void kernel_launch(void* const* d_in, const int* in_sizes, int n_in,
                              void* d_out, int out_size)
{
    const float* charge  = (const float*)d_in[0];
    const float* shell   = (const float*)d_in[1];
    const float* mass    = (const float*)d_in[2];
    const float* valence = (const float*)d_in[3];
    // d_in[4] = position (arange; recomputed from indices)
    const float* x       = (const float*)d_in[5];
    const float* Wv      = (const float*)d_in[6];
    const float* bv      = (const float*)d_in[7];
    const float* Wo      = (const float*)d_in[8];
    const float* bo      = (const float*)d_in[9];
    float* out = (float*)d_out;

    void* pV = nullptr;
    void* pP = nullptr;
    cudaGetSymbolAddress(&pV, g_V);
    cudaGetSymbolAddress(&pP, g_P);

    const int smem_bytes = SMEM_FLOATS * (int)sizeof(float);
    cudaFuncSetAttribute(attn_kernel,
                         cudaFuncAttributeMaxDynamicSharedMemorySize, smem_bytes);

    dim3 gg(M_/64, 4);
    // 1) V = x @ Wv^T + bv  -> g_V (padded to 256 cols, pad = 0)
    gemm_bias_kernel<<<gg, 256>>>(x, D_, Wv, bv, (float*)pV, DP_, DP_);
    // 2) fused attention -> g_P
    attn_kernel<<<dim3(64, B_), 256, smem_bytes>>>(charge, shell, mass, valence);
    // 3) out = g_P @ Wo^T + bo
    gemm_bias_kernel<<<gg, 256>>>((const float*)pP, DP_, Wo, bo, out, D_, D_);
}